// round 2
// baseline (speedup 1.0000x reference)
#include <cuda_runtime.h>
#include <cstdint>

#define NB_EVENT 2000
#define NB_TYPE  10
#define PRED_LEN 1000
#define RBLK     8
#define NBLK     (PRED_LEN / RBLK)      // 125
#define NTHREADS 512

// ---- dynamic shared memory layout (float offsets) ----
#define OFF_F    0            // f_t (term1)            [10000]
#define OFF_C    10000        // c_{t,i} then preds     [10000]
#define OFF_U    20000        // u double buffer        [2*1250]  (h = buf0 at end)
#define OFF_M    22500        // M                      [100]
#define OFF_R    22600        // R_0..R_7 (R_0 = B)     [800]
#define OFF_T    23400        // M^2                    [100]
#define OFF_T2   23500        // M^4                    [100]
#define OFF_P8   23600        // M^8                    [100]
#define OFF_S0   23700        // S0                     [16]
#define OFF_EW   23716        // exp(-w)                [16]
#define OFF_OM   23732        // 1-exp(-w)              [16]
#define OFF_RW   23748        // 1/w                    [16]
#define OFF_TH   23764        // theta                  [16]
#define OFF_SP   23780        // spont                  [16]
#define SMEM_FLOATS 23808
#define SMEM_BYTES  (SMEM_FLOATS * 4)

extern __shared__ float sm[];

__global__ __launch_bounds__(NTHREADS, 1)
void hawkes_kernel(const int* __restrict__ seq_id,
                   const float* __restrict__ sequences,
                   const float* __restrict__ spontaneous,
                   const float* __restrict__ theta,
                   const float* __restrict__ w,
                   const float* __restrict__ alpha,
                   float* __restrict__ out)
{
    float* __restrict__ sf  = sm + OFF_F;
    float* __restrict__ sc  = sm + OFF_C;
    float* __restrict__ su  = sm + OFF_U;
    float* __restrict__ sM  = sm + OFF_M;
    float* __restrict__ sR  = sm + OFF_R;
    float* __restrict__ sT  = sm + OFF_T;
    float* __restrict__ sT2 = sm + OFF_T2;
    float* __restrict__ sP8 = sm + OFF_P8;
    float* __restrict__ sS0 = sm + OFF_S0;
    float* __restrict__ sew = sm + OFF_EW;
    float* __restrict__ som = sm + OFF_OM;
    float* __restrict__ srw = sm + OFF_RW;
    float* __restrict__ sth = sm + OFF_TH;
    float* __restrict__ ssp = sm + OFF_SP;

    const int tid  = threadIdx.x;
    const int wid  = tid >> 5;
    const int lane = tid & 31;

    const int sid = seq_id[0];
    const float* __restrict__ seq = sequences + (size_t)sid * NB_EVENT * NB_TYPE;

    // ---- per-type params ----
    if (tid < NB_TYPE) {
        const float wk = w[sid * NB_TYPE + tid];
        const float e  = expf(-wk);
        sew[tid] = e;
        som[tid] = 1.0f - e;
        srw[tid] = 1.0f / wk;
        sth[tid] = theta[sid * NB_TYPE + tid];
        ssp[tid] = spontaneous[sid * NB_TYPE + tid];
    }
    // zero u buffer 0 (u_0 = 0)
    for (int i = tid; i < NBLK * NB_TYPE; i += NTHREADS) su[i] = 0.0f;
    __syncthreads();

    // ---- Phase A: copy training block to out (float4 coalesced) ----
    {
        const float4* __restrict__ s4 = (const float4*)seq;
        float4* __restrict__ o4 = (float4*)out;
        #pragma unroll 2
        for (int i = tid; i < (NB_EVENT * NB_TYPE) / 4; i += NTHREADS)
            o4[i] = s4[i];
    }

    // ---- Phase C: forcing f_t = term1 for all 1000 steps ----
    for (int idx = tid; idx < PRED_LEN * NB_TYPE; idx += NTHREADS) {
        const int i = idx / NB_TYPE;
        const int k = idx - i * NB_TYPE;
        const float th = sth[k];
        const float t  = (float)(NB_EVENT + i);
        sf[idx] = ssp[k] / th * (expf(-th * t) - expf(-th * (t + 1.0f)));
    }

    // ---- Phase D: build B (into R_0) and M ----
    if (tid < 100) {
        const int k = tid / 10, j = tid - (tid / 10) * 10;
        const float b = srw[k] * alpha[((size_t)sid * NB_TYPE + k) * NB_TYPE + j] * som[j];
        sR[tid] = b;                                       // R_0 = B
        sM[tid] = sew[k] * ((k == j ? 1.0f : 0.0f) + b);   // M = diag(ew)(I+B)
    }

    // ---- Phase B: S0[k] = sum_e seq[e][k] * exp(-w_k*(2000-e)), warp per k ----
    if (wid < NB_TYPE) {
        const int k = wid;
        const float wk = w[sid * NB_TYPE + k];
        float acc = 0.0f;
        for (int e = lane; e < NB_EVENT; e += 32)
            acc += seq[e * NB_TYPE + k] * expf(-wk * (float)(NB_EVENT - e));
        #pragma unroll
        for (int off = 16; off > 0; off >>= 1)
            acc += __shfl_xor_sync(0xFFFFFFFFu, acc, off);
        if (lane == 0) sS0[k] = acc;
    }
    __syncthreads();

    // ---- Phases E+G interleaved, 8 sync rounds ----
    // E (threads 0..199): R_{i+1} = R_i * M chain (7 steps) + M^8 by squaring (3 steps)
    // G (all threads):    batched u recurrence over 125 blocks; writes c, final u = h
    for (int rd = 0; rd < 8; rd++) {
        if (tid < 100) {
            if (rd < 7) {
                const int k = tid / 10, j = tid - (tid / 10) * 10;
                float acc = 0.0f;
                #pragma unroll
                for (int m = 0; m < 10; m++)
                    acc += sR[rd * 100 + k * 10 + m] * sM[m * 10 + j];
                sR[(rd + 1) * 100 + k * 10 + j] = acc;
            }
        } else if (tid < 200) {
            const int p = tid - 100;
            const int k = p / 10, j = p - (p / 10) * 10;
            if (rd == 0) {
                float acc = 0.0f;
                #pragma unroll
                for (int m = 0; m < 10; m++) acc += sM[k * 10 + m] * sM[m * 10 + j];
                sT[p] = acc;                 // M^2
            } else if (rd == 1) {
                float acc = 0.0f;
                #pragma unroll
                for (int m = 0; m < 10; m++) acc += sT[k * 10 + m] * sT[m * 10 + j];
                sT2[p] = acc;                // M^4
            } else if (rd == 2) {
                float acc = 0.0f;
                #pragma unroll
                for (int m = 0; m < 10; m++) acc += sT2[k * 10 + m] * sT2[m * 10 + j];
                sP8[p] = acc;                // M^8
            }
        }

        // G: fused pass — c_{t,rd} = f + B*u ; u <- M*u + ew⊙f
        {
            const float* __restrict__ uc = su + (rd & 1) * (NBLK * NB_TYPE);
            float* __restrict__ un = su + ((rd & 1) ^ 1) * (NBLK * NB_TYPE);
            for (int item = tid; item < NBLK * NB_TYPE; item += NTHREADS) {
                const int t = item / NB_TYPE;
                const int k = item - t * NB_TYPE;
                const int base = (t * RBLK + rd) * NB_TYPE;
                const float fv = sf[base + k];
                float ca = fv;
                float ua = sew[k] * fv;
                #pragma unroll
                for (int m = 0; m < 10; m++) {
                    const float um = uc[t * NB_TYPE + m];
                    ca += sR[k * 10 + m] * um;   // B = R_0
                    ua += sM[k * 10 + m] * um;
                }
                sc[base + k] = ca;
                un[item] = ua;
            }
        }
        __syncthreads();
    }
    // after 8 rounds: su (buf 0) holds h_t = u_{t,8}

    // ---- Phase S: serial scan, warp 0, 125 iterations of 8 steps each ----
    if (wid == 0) {
        const bool act = (lane < NB_TYPE);
        const int  k   = act ? lane : 0;

        float Rr[RBLK][10];
        float P8r[10];
        #pragma unroll
        for (int i = 0; i < RBLK; i++)
            #pragma unroll
            for (int m = 0; m < 10; m++)
                Rr[i][m] = sR[i * 100 + k * 10 + m];
        #pragma unroll
        for (int m = 0; m < 10; m++) P8r[m] = sP8[k * 10 + m];

        float S = sS0[k];

        for (int t = 0; t < NBLK; t++) {
            const float s0 = __shfl_sync(0xFFFFFFFFu, S, 0);
            const float s1 = __shfl_sync(0xFFFFFFFFu, S, 1);
            const float s2 = __shfl_sync(0xFFFFFFFFu, S, 2);
            const float s3 = __shfl_sync(0xFFFFFFFFu, S, 3);
            const float s4 = __shfl_sync(0xFFFFFFFFu, S, 4);
            const float s5 = __shfl_sync(0xFFFFFFFFu, S, 5);
            const float s6 = __shfl_sync(0xFFFFFFFFu, S, 6);
            const float s7 = __shfl_sync(0xFFFFFFFFu, S, 7);
            const float s8 = __shfl_sync(0xFFFFFFFFu, S, 8);
            const float s9 = __shfl_sync(0xFFFFFFFFu, S, 9);

            const int cb = t * (RBLK * NB_TYPE) + k;
            #pragma unroll
            for (int i = 0; i < RBLK; i++) {
                float p = sc[cb + i * NB_TYPE];
                p += Rr[i][0] * s0; p += Rr[i][1] * s1;
                p += Rr[i][2] * s2; p += Rr[i][3] * s3;
                p += Rr[i][4] * s4; p += Rr[i][5] * s5;
                p += Rr[i][6] * s6; p += Rr[i][7] * s7;
                p += Rr[i][8] * s8; p += Rr[i][9] * s9;
                if (act) sc[cb + i * NB_TYPE] = p;   // overwrite c with pred
            }

            float Sn = su[t * NB_TYPE + k];          // h_t
            Sn += P8r[0] * s0; Sn += P8r[1] * s1;
            Sn += P8r[2] * s2; Sn += P8r[3] * s3;
            Sn += P8r[4] * s4; Sn += P8r[5] * s5;
            Sn += P8r[6] * s6; Sn += P8r[7] * s7;
            Sn += P8r[8] * s8; Sn += P8r[9] * s9;
            S = Sn;
        }
    }
    __syncthreads();

    // ---- drain predictions smem -> gmem (float4 coalesced) ----
    {
        const float4* __restrict__ c4 = (const float4*)sc;
        float4* __restrict__ o4 = (float4*)(out + NB_EVENT * NB_TYPE);
        #pragma unroll 2
        for (int i = tid; i < (PRED_LEN * NB_TYPE) / 4; i += NTHREADS)
            o4[i] = c4[i];
    }
}

extern "C" void kernel_launch(void* const* d_in, const int* in_sizes, int n_in,
                              void* d_out, int out_size)
{
    const int*   seq_id      = (const int*)  d_in[0];
    const float* sequences   = (const float*)d_in[1];
    const float* spontaneous = (const float*)d_in[2];
    const float* theta       = (const float*)d_in[3];
    const float* w           = (const float*)d_in[4];
    const float* alpha       = (const float*)d_in[5];
    float* out = (float*)d_out;

    cudaFuncSetAttribute(hawkes_kernel,
                         cudaFuncAttributeMaxDynamicSharedMemorySize, SMEM_BYTES);
    hawkes_kernel<<<1, NTHREADS, SMEM_BYTES>>>(seq_id, sequences, spontaneous,
                                               theta, w, alpha, out);
}

// round 3
// speedup vs baseline: 2.0491x; 2.0491x over previous
#include <cuda_runtime.h>
#include <cstdint>

#define NB_EVENT 2000
#define NB_TYPE  10
#define PRED_LEN 1000
#define RBLK     8
#define NBLK     (PRED_LEN / RBLK)      // 125
#define NTHREADS 512
#define SEQT_STRIDE 2004

// ---- dynamic shared memory layout (float offsets) ----
#define OFF_F    0            // f_t forcing             [10000]
#define OFF_C    10000        // c_{t,i} then preds      [10000]
#define OFF_U    20000        // u double buffer         [2*1250]
#define OFF_M    22500        // M                       [100]
#define OFF_R    22600        // R_0..R_7 (R_0 = B)      [800]
#define OFF_T    23400        // M^2                     [100]
#define OFF_T2   23500        // M^4                     [100]
#define OFF_P8   23600        // M^8                     [100]
#define OFF_ST   23700        // S_t for t=0..124        [1250]
#define OFF_S0   24950        // S0                      [16]
#define OFF_EW   24966        // exp(-w)                 [16]
#define OFF_OM   24982        // 1-exp(-w)               [16]
#define OFF_RW   24998        // 1/w                     [16]
#define OFF_TH   25014        // theta                   [16]
#define OFF_SP   25030        // spont                   [16]
#define OFF_AK   25046        // (sp/th)*(1-exp(-th))    [16]
#define OFF_W    25062        // w                       [16]
#define OFF_SEQT 25088        // transposed seq [10][2004]
#define SMEM_FLOATS (OFF_SEQT + NB_TYPE * SEQT_STRIDE)   // 45128
#define SMEM_BYTES  (SMEM_FLOATS * 4)                    // 180512

extern __shared__ float sm[];

__global__ __launch_bounds__(NTHREADS, 1)
void hawkes_kernel(const int* __restrict__ seq_id,
                   const float* __restrict__ sequences,
                   const float* __restrict__ spontaneous,
                   const float* __restrict__ theta,
                   const float* __restrict__ w,
                   const float* __restrict__ alpha,
                   float* __restrict__ out)
{
    float* __restrict__ sf   = sm + OFF_F;
    float* __restrict__ sc   = sm + OFF_C;
    float* __restrict__ su   = sm + OFF_U;
    float* __restrict__ sM   = sm + OFF_M;
    float* __restrict__ sR   = sm + OFF_R;
    float* __restrict__ sT   = sm + OFF_T;
    float* __restrict__ sT2  = sm + OFF_T2;
    float* __restrict__ sP8  = sm + OFF_P8;
    float* __restrict__ sSt  = sm + OFF_ST;
    float* __restrict__ sS0  = sm + OFF_S0;
    float* __restrict__ sew  = sm + OFF_EW;
    float* __restrict__ som  = sm + OFF_OM;
    float* __restrict__ srw  = sm + OFF_RW;
    float* __restrict__ sth  = sm + OFF_TH;
    float* __restrict__ ssp  = sm + OFF_SP;
    float* __restrict__ sak  = sm + OFF_AK;
    float* __restrict__ sW   = sm + OFF_W;
    float* __restrict__ sqT  = sm + OFF_SEQT;

    const int tid  = threadIdx.x;
    const int wid  = tid >> 5;
    const int lane = tid & 31;

    const int sid = seq_id[0];
    const float* __restrict__ seq = sequences + (size_t)sid * NB_EVENT * NB_TYPE;

    // ---- per-type params + forcing prefactor ----
    if (tid < NB_TYPE) {
        const float wk = w[sid * NB_TYPE + tid];
        const float e  = expf(-wk);
        const float th = theta[sid * NB_TYPE + tid];
        const float sp = spontaneous[sid * NB_TYPE + tid];
        sW[tid]  = wk;
        sew[tid] = e;
        som[tid] = 1.0f - e;
        srw[tid] = 1.0f / wk;
        sth[tid] = th;
        ssp[tid] = sp;
        sak[tid] = sp / th * (1.0f - expf(-th));
    }
    // zero u buffer 0 (u_0 = 0)
    for (int i = tid; i < NBLK * NB_TYPE; i += NTHREADS) su[i] = 0.0f;
    __syncthreads();

    // ---- Phase A: copy training block to out + transpose into smem ----
    {
        const float4* __restrict__ s4 = (const float4*)seq;
        float4* __restrict__ o4 = (float4*)out;
        for (int i = tid; i < (NB_EVENT * NB_TYPE) / 4; i += NTHREADS) {
            const float4 v = s4[i];
            o4[i] = v;
            const int p = i * 4;
            int e0 = p / 10, k0 = p - e0 * 10;
            sqT[k0 * SEQT_STRIDE + e0] = v.x;
            int p1 = p + 1; int e1 = p1 / 10, k1 = p1 - e1 * 10;
            sqT[k1 * SEQT_STRIDE + e1] = v.y;
            int p2 = p + 2; int e2 = p2 / 10, k2 = p2 - e2 * 10;
            sqT[k2 * SEQT_STRIDE + e2] = v.z;
            int p3 = p + 3; int e3 = p3 / 10, k3 = p3 - e3 * 10;
            sqT[k3 * SEQT_STRIDE + e3] = v.w;
        }
    }

    // ---- Phase C: forcing f[i][k] = A_k * exp(-th_k*(2000+i)) ----
    for (int idx = tid; idx < PRED_LEN * NB_TYPE; idx += NTHREADS) {
        const int i = idx / NB_TYPE;
        const int k = idx - i * NB_TYPE;
        sf[idx] = sak[k] * expf(-sth[k] * (float)(NB_EVENT + i));
    }

    // ---- Phase D: build B (= R_0) and M = diag(ew)(I+B) ----
    if (tid < 100) {
        const int k = tid / 10, j = tid - (tid / 10) * 10;
        const float b = srw[k] * alpha[((size_t)sid * NB_TYPE + k) * NB_TYPE + j] * som[j];
        sR[tid] = b;
        sM[tid] = sew[k] * ((k == j ? 1.0f : 0.0f) + b);
    }
    __syncthreads();

    // ---- Phase B: S0[k] via transposed smem (coalesced LDS), warp per k ----
    if (wid < NB_TYPE) {
        const int k = wid;
        const float wk = sW[k];
        float acc = 0.0f;
        for (int e = lane; e < NB_EVENT; e += 32)
            acc += sqT[k * SEQT_STRIDE + e] * expf(wk * (float)(e - NB_EVENT));
        #pragma unroll
        for (int off = 16; off > 0; off >>= 1)
            acc += __shfl_xor_sync(0xFFFFFFFFu, acc, off);
        if (lane == 0) sS0[k] = acc;
    }
    __syncthreads();

    // ---- Phases E+G interleaved, 8 rounds ----
    // E: R_{i+1} = R_i*M (threads 0..99); M^2,M^4,M^8 (threads 100..199)
    // G: batched u recurrence over 125 blocks; emits c_{t,rd}
    for (int rd = 0; rd < 8; rd++) {
        if (tid < 100) {
            if (rd < 7) {
                const int k = tid / 10, j = tid - (tid / 10) * 10;
                float acc = 0.0f;
                #pragma unroll
                for (int m = 0; m < 10; m++)
                    acc += sR[rd * 100 + k * 10 + m] * sM[m * 10 + j];
                sR[(rd + 1) * 100 + k * 10 + j] = acc;
            }
        } else if (tid < 200) {
            const int p = tid - 100;
            const int k = p / 10, j = p - (p / 10) * 10;
            if (rd == 0) {
                float acc = 0.0f;
                #pragma unroll
                for (int m = 0; m < 10; m++) acc += sM[k * 10 + m] * sM[m * 10 + j];
                sT[p] = acc;
            } else if (rd == 1) {
                float acc = 0.0f;
                #pragma unroll
                for (int m = 0; m < 10; m++) acc += sT[k * 10 + m] * sT[m * 10 + j];
                sT2[p] = acc;
            } else if (rd == 2) {
                float acc = 0.0f;
                #pragma unroll
                for (int m = 0; m < 10; m++) acc += sT2[k * 10 + m] * sT2[m * 10 + j];
                sP8[p] = acc;
            }
        }
        {
            const float* __restrict__ uc = su + (rd & 1) * (NBLK * NB_TYPE);
            float* __restrict__ un = su + ((rd & 1) ^ 1) * (NBLK * NB_TYPE);
            for (int item = tid; item < NBLK * NB_TYPE; item += NTHREADS) {
                const int t = item / NB_TYPE;
                const int k = item - t * NB_TYPE;
                const int base = (t * RBLK + rd) * NB_TYPE;
                const float fv = sf[base + k];
                float ca = fv;
                float ua = sew[k] * fv;
                #pragma unroll
                for (int m = 0; m < 10; m++) {
                    const float um = uc[t * NB_TYPE + m];
                    ca += sR[k * 10 + m] * um;   // B = R_0
                    ua += sM[k * 10 + m] * um;
                }
                sc[base + k] = ca;
                un[item] = ua;
            }
        }
        __syncthreads();
    }
    // su buf0 now holds h_t = u_{t,8}

    // ---- Phase S: minimal serial scan (warp 0). Emits S_t into sSt. ----
    if (wid == 0) {
        const bool act = (lane < NB_TYPE);
        const int  k   = act ? lane : 0;

        float P8r[10];
        #pragma unroll
        for (int m = 0; m < 10; m++) P8r[m] = sP8[k * 10 + m];

        float S = act ? sS0[k] : 0.0f;
        if (act) sSt[k] = S;

        for (int t = 0; t < NBLK - 1; t++) {
            const float s0 = __shfl_sync(0xFFFFFFFFu, S, 0);
            const float s1 = __shfl_sync(0xFFFFFFFFu, S, 1);
            const float s2 = __shfl_sync(0xFFFFFFFFu, S, 2);
            const float s3 = __shfl_sync(0xFFFFFFFFu, S, 3);
            const float s4 = __shfl_sync(0xFFFFFFFFu, S, 4);
            const float s5 = __shfl_sync(0xFFFFFFFFu, S, 5);
            const float s6 = __shfl_sync(0xFFFFFFFFu, S, 6);
            const float s7 = __shfl_sync(0xFFFFFFFFu, S, 7);
            const float s8 = __shfl_sync(0xFFFFFFFFu, S, 8);
            const float s9 = __shfl_sync(0xFFFFFFFFu, S, 9);

            const float p0 = P8r[0] * s0, p1 = P8r[1] * s1;
            const float p2 = P8r[2] * s2, p3 = P8r[3] * s3;
            const float p4 = P8r[4] * s4, p5 = P8r[5] * s5;
            const float p6 = P8r[6] * s6, p7 = P8r[7] * s7;
            const float p8 = P8r[8] * s8, p9 = P8r[9] * s9;
            const float q0 = p0 + p1, q1 = p2 + p3, q2 = p4 + p5;
            const float q3 = p6 + p7, q4 = p8 + p9;
            const float h  = su[t * NB_TYPE + k];            // off-chain load
            const float r0 = q0 + q1, r1 = q2 + q3, r2 = q4 + h;
            S = (r0 + r1) + r2;
            if (act) sSt[(t + 1) * NB_TYPE + k] = S;
        }
    }
    __syncthreads();

    // ---- Phase P: parallel pred evaluation: pred = c + R_i * S_t ----
    for (int item = tid; item < NBLK * NB_TYPE; item += NTHREADS) {
        const int t = item / NB_TYPE;
        const int k = item - t * NB_TYPE;
        float Sv[10];
        #pragma unroll
        for (int m = 0; m < 10; m++) Sv[m] = sSt[t * NB_TYPE + m];
        const int base = t * (RBLK * NB_TYPE) + k;
        #pragma unroll
        for (int i = 0; i < RBLK; i++) {
            float acc = sc[base + i * NB_TYPE];
            #pragma unroll
            for (int m = 0; m < 10; m++)
                acc += sR[i * 100 + k * 10 + m] * Sv[m];
            sc[base + i * NB_TYPE] = acc;
        }
    }
    __syncthreads();

    // ---- drain predictions smem -> gmem (float4 coalesced) ----
    {
        const float4* __restrict__ c4 = (const float4*)sc;
        float4* __restrict__ o4 = (float4*)(out + NB_EVENT * NB_TYPE);
        for (int i = tid; i < (PRED_LEN * NB_TYPE) / 4; i += NTHREADS)
            o4[i] = c4[i];
    }
}

extern "C" void kernel_launch(void* const* d_in, const int* in_sizes, int n_in,
                              void* d_out, int out_size)
{
    const int*   seq_id      = (const int*)  d_in[0];
    const float* sequences   = (const float*)d_in[1];
    const float* spontaneous = (const float*)d_in[2];
    const float* theta       = (const float*)d_in[3];
    const float* w           = (const float*)d_in[4];
    const float* alpha       = (const float*)d_in[5];
    float* out = (float*)d_out;

    cudaFuncSetAttribute(hawkes_kernel,
                         cudaFuncAttributeMaxDynamicSharedMemorySize, SMEM_BYTES);
    hawkes_kernel<<<1, NTHREADS, SMEM_BYTES>>>(seq_id, sequences, spontaneous,
                                               theta, w, alpha, out);
}

// round 4
// speedup vs baseline: 2.6386x; 1.2877x over previous
#include <cuda_runtime.h>
#include <cstdint>

#define NB_EVENT 2000
#define NB_TYPE  10
#define PRED_LEN 1000
#define RBLK     20
#define NBLK     (PRED_LEN / RBLK)      // 50
#define NTHREADS 512
#define SEQB     512                     // tail events that can contribute (w>=0.5 -> older are exactly 0 in f32)
#define E0       (NB_EVENT - SEQB)       // 1488
#define SEQB_STRIDE 520

// ---- dynamic shared memory layout (float offsets) ----
#define OFF_F    0                       // forcing f            [10000]
#define OFF_C    10000                   // c then preds         [10000]
#define OFF_U    20000                   // u double buffer      [1000]
#define OFF_M    21000                   // M                    [100]
#define OFF_R    21100                   // R_0..R_19 (R_0=B)    [2000]
#define OFF_M2   23100                   // M^2                  [100]
#define OFF_M4   23200                   // M^4                  [100]
#define OFF_M8   23300                   // M^8                  [100]
#define OFF_M16  23400                   // M^16                 [100]
#define OFF_P    23500                   // M^20                 [100]
#define OFF_ST   23600                   // S_t, t=0..49         [500]
#define OFF_S0   24100                   // S0                   [16]
#define OFF_EW   24116                   // exp(-w)              [16]
#define OFF_OM   24132                   // 1-exp(-w)            [16]
#define OFF_RW   24148                   // 1/w                  [16]
#define OFF_TH   24164                   // theta                [16]
#define OFF_AK   24180                   // sp/th*(1-exp(-th))   [16]
#define OFF_W    24196                   // w                    [16]
#define OFF_ER   24212                   // exp(-th)             [16]
#define OFF_SEQT 24240                   // tail transpose [10][520]
#define SMEM_FLOATS (OFF_SEQT + NB_TYPE * SEQB_STRIDE)   // 29440
#define SMEM_BYTES  (SMEM_FLOATS * 4)

extern __shared__ float sm[];

__global__ __launch_bounds__(NTHREADS, 1)
void hawkes_kernel(const int* __restrict__ seq_id,
                   const float* __restrict__ sequences,
                   const float* __restrict__ spontaneous,
                   const float* __restrict__ theta,
                   const float* __restrict__ w,
                   const float* __restrict__ alpha,
                   float* __restrict__ out)
{
    float* __restrict__ sf   = sm + OFF_F;
    float* __restrict__ sc   = sm + OFF_C;
    float* __restrict__ su   = sm + OFF_U;
    float* __restrict__ sM   = sm + OFF_M;
    float* __restrict__ sR   = sm + OFF_R;
    float* __restrict__ sM2  = sm + OFF_M2;
    float* __restrict__ sM4  = sm + OFF_M4;
    float* __restrict__ sM8  = sm + OFF_M8;
    float* __restrict__ sM16 = sm + OFF_M16;
    float* __restrict__ sP   = sm + OFF_P;
    float* __restrict__ sSt  = sm + OFF_ST;
    float* __restrict__ sS0  = sm + OFF_S0;
    float* __restrict__ sew  = sm + OFF_EW;
    float* __restrict__ som  = sm + OFF_OM;
    float* __restrict__ srw  = sm + OFF_RW;
    float* __restrict__ sth  = sm + OFF_TH;
    float* __restrict__ sak  = sm + OFF_AK;
    float* __restrict__ sW   = sm + OFF_W;
    float* __restrict__ sER  = sm + OFF_ER;
    float* __restrict__ sqT  = sm + OFF_SEQT;

    const int tid  = threadIdx.x;
    const int wid  = tid >> 5;
    const int lane = tid & 31;

    const int sid = seq_id[0];
    const float* __restrict__ seq = sequences + (size_t)sid * NB_EVENT * NB_TYPE;

    // ---- per-type params (10 expf total here) ----
    if (tid < NB_TYPE) {
        const float wk = w[sid * NB_TYPE + tid];
        const float e  = expf(-wk);
        const float th = theta[sid * NB_TYPE + tid];
        const float sp = spontaneous[sid * NB_TYPE + tid];
        const float er = expf(-th);
        sW[tid]  = wk;
        sew[tid] = e;
        som[tid] = 1.0f - e;
        srw[tid] = 1.0f / wk;
        sth[tid] = th;
        sak[tid] = sp / th * (1.0f - er);
        sER[tid] = er;
    }
    for (int i = tid; i < NBLK * NB_TYPE; i += NTHREADS) su[i] = 0.0f;  // u_0 = 0
    __syncthreads();

    // ---- Phase A: copy full training block to out; transpose tail into smem ----
    {
        const float4* __restrict__ s4 = (const float4*)seq;
        float4* __restrict__ o4 = (float4*)out;
        for (int i = tid; i < (NB_EVENT * NB_TYPE) / 4; i += NTHREADS) {
            const float4 v = s4[i];
            o4[i] = v;
            if (i >= (E0 * NB_TYPE) / 4) {          // 14880/4 = 3720, exact
                const int p = i * 4;
                int e0 = p / 10, k0 = p - e0 * 10;
                sqT[k0 * SEQB_STRIDE + (e0 - E0)] = v.x;
                int p1 = p + 1, e1 = p1 / 10, k1 = p1 - e1 * 10;
                sqT[k1 * SEQB_STRIDE + (e1 - E0)] = v.y;
                int p2 = p + 2, e2 = p2 / 10, k2 = p2 - e2 * 10;
                sqT[k2 * SEQB_STRIDE + (e2 - E0)] = v.z;
                int p3 = p + 3, e3 = p3 / 10, k3 = p3 - e3 * 10;
                sqT[k3 * SEQB_STRIDE + (e3 - E0)] = v.w;
            }
        }
    }

    // ---- Phase C: forcing via geometric recurrence (500 expf total) ----
    if (tid < 500) {
        const int k = tid % 10;
        const int c = tid / 10;               // chunk of 20 steps
        const float r = sER[k];
        float v = sak[k] * expf(-sth[k] * (float)(NB_EVENT + c * 20));
        #pragma unroll
        for (int j = 0; j < 20; j++) {
            sf[(c * 20 + j) * NB_TYPE + k] = v;
            v *= r;
        }
    }

    // ---- Phase D: B (=R_0) and M = diag(ew)(I+B) ----
    if (tid < 100) {
        const int k = tid / 10, j = tid - (tid / 10) * 10;
        const float b = srw[k] * alpha[((size_t)sid * NB_TYPE + k) * NB_TYPE + j] * som[j];
        sR[tid] = b;
        sM[tid] = sew[k] * ((k == j ? 1.0f : 0.0f) + b);
    }
    __syncthreads();

    // ---- Phase B: S0 via downward geometric decay (2 expf per lane) ----
    if (wid < NB_TYPE) {
        const int k = wid;
        const float wk = sW[k];
        float d = expf(-wk * (float)(1 + lane));       // decay at e = 1999 - lane
        const float r = expf(-32.0f * wk);
        float acc = 0.0f;
        #pragma unroll
        for (int j = 0; j < SEQB / 32; j++) {          // 16 iters, e descending
            const int idx = (SEQB - 1 - lane) - 32 * j;
            acc += sqT[k * SEQB_STRIDE + idx] * d;
            d *= r;
        }
        #pragma unroll
        for (int off = 16; off > 0; off >>= 1)
            acc += __shfl_xor_sync(0xFFFFFFFFu, acc, off);
        if (lane == 0) sS0[k] = acc;
    }
    __syncthreads();

    // ---- Phases E+G interleaved, RBLK rounds ----
    for (int rd = 0; rd < RBLK; rd++) {
        if (tid < 100) {
            if (rd < RBLK - 1) {                       // R chain
                const int k = tid / 10, j = tid - (tid / 10) * 10;
                float acc = 0.0f;
                #pragma unroll
                for (int m = 0; m < 10; m++)
                    acc += sR[rd * 100 + k * 10 + m] * sM[m * 10 + j];
                sR[(rd + 1) * 100 + k * 10 + j] = acc;
            }
        } else if (tid < 200) {                        // M^20 by squaring chain
            const int p = tid - 100;
            const int k = p / 10, j = p - (p / 10) * 10;
            float acc = 0.0f;
            if (rd == 0) {
                #pragma unroll
                for (int m = 0; m < 10; m++) acc += sM[k * 10 + m] * sM[m * 10 + j];
                sM2[p] = acc;
            } else if (rd == 1) {
                #pragma unroll
                for (int m = 0; m < 10; m++) acc += sM2[k * 10 + m] * sM2[m * 10 + j];
                sM4[p] = acc;
            } else if (rd == 2) {
                #pragma unroll
                for (int m = 0; m < 10; m++) acc += sM4[k * 10 + m] * sM4[m * 10 + j];
                sM8[p] = acc;
            } else if (rd == 3) {
                #pragma unroll
                for (int m = 0; m < 10; m++) acc += sM8[k * 10 + m] * sM8[m * 10 + j];
                sM16[p] = acc;
            } else if (rd == 4) {
                #pragma unroll
                for (int m = 0; m < 10; m++) acc += sM16[k * 10 + m] * sM4[m * 10 + j];
                sP[p] = acc;                           // M^20
            }
        }
        // G: u recurrence over 50 blocks; emit c_{t,rd}
        {
            const float* __restrict__ uc = su + (rd & 1) * (NBLK * NB_TYPE);
            float* __restrict__ un = su + ((rd & 1) ^ 1) * (NBLK * NB_TYPE);
            if (tid < NBLK * NB_TYPE) {
                const int t = tid / NB_TYPE;
                const int k = tid - t * NB_TYPE;
                const int base = (t * RBLK + rd) * NB_TYPE;
                const float fv = sf[base + k];
                float ca = fv;
                float ua = sew[k] * fv;
                #pragma unroll
                for (int m = 0; m < 10; m++) {
                    const float um = uc[t * NB_TYPE + m];
                    ca += sR[k * 10 + m] * um;         // B = R_0
                    ua += sM[k * 10 + m] * um;
                }
                sc[base + k] = ca;
                un[tid] = ua;
            }
        }
        __syncthreads();
    }
    // su buf0 holds h_t = u_{t,20}

    // ---- Phase S: minimal serial scan (warp 0), 49 iterations ----
    if (wid == 0) {
        const bool act = (lane < NB_TYPE);
        const int  k   = act ? lane : 0;
        float Pr[10];
        #pragma unroll
        for (int m = 0; m < 10; m++) Pr[m] = sP[k * 10 + m];

        float S = act ? sS0[k] : 0.0f;
        if (act) sSt[k] = S;

        for (int t = 0; t < NBLK - 1; t++) {
            const float s0 = __shfl_sync(0xFFFFFFFFu, S, 0);
            const float s1 = __shfl_sync(0xFFFFFFFFu, S, 1);
            const float s2 = __shfl_sync(0xFFFFFFFFu, S, 2);
            const float s3 = __shfl_sync(0xFFFFFFFFu, S, 3);
            const float s4 = __shfl_sync(0xFFFFFFFFu, S, 4);
            const float s5 = __shfl_sync(0xFFFFFFFFu, S, 5);
            const float s6 = __shfl_sync(0xFFFFFFFFu, S, 6);
            const float s7 = __shfl_sync(0xFFFFFFFFu, S, 7);
            const float s8 = __shfl_sync(0xFFFFFFFFu, S, 8);
            const float s9 = __shfl_sync(0xFFFFFFFFu, S, 9);

            const float p0 = Pr[0] * s0, p1 = Pr[1] * s1;
            const float p2 = Pr[2] * s2, p3 = Pr[3] * s3;
            const float p4 = Pr[4] * s4, p5 = Pr[5] * s5;
            const float p6 = Pr[6] * s6, p7 = Pr[7] * s7;
            const float p8 = Pr[8] * s8, p9 = Pr[9] * s9;
            const float h  = su[t * NB_TYPE + k];
            const float q0 = p0 + p1, q1 = p2 + p3, q2 = p4 + p5;
            const float q3 = p6 + p7, q4 = p8 + p9;
            const float r0 = q0 + q1, r1 = q2 + q3, r2 = q4 + h;
            S = (r0 + r1) + r2;
            if (act) sSt[(t + 1) * NB_TYPE + k] = S;
        }
    }
    __syncthreads();

    // ---- Phase P: parallel pred = c + R_i * S_t ----
    if (tid < NBLK * NB_TYPE) {
        const int t = tid / NB_TYPE;
        const int k = tid - t * NB_TYPE;
        float Sv[10];
        #pragma unroll
        for (int m = 0; m < 10; m++) Sv[m] = sSt[t * NB_TYPE + m];
        const int base = t * (RBLK * NB_TYPE) + k;
        #pragma unroll
        for (int i = 0; i < RBLK; i++) {
            float acc = sc[base + i * NB_TYPE];
            #pragma unroll
            for (int m = 0; m < 10; m++)
                acc += sR[i * 100 + k * 10 + m] * Sv[m];
            sc[base + i * NB_TYPE] = acc;
        }
    }
    __syncthreads();

    // ---- drain predictions smem -> gmem ----
    {
        const float4* __restrict__ c4 = (const float4*)sc;
        float4* __restrict__ o4 = (float4*)(out + NB_EVENT * NB_TYPE);
        for (int i = tid; i < (PRED_LEN * NB_TYPE) / 4; i += NTHREADS)
            o4[i] = c4[i];
    }
}

extern "C" void kernel_launch(void* const* d_in, const int* in_sizes, int n_in,
                              void* d_out, int out_size)
{
    const int*   seq_id      = (const int*)  d_in[0];
    const float* sequences   = (const float*)d_in[1];
    const float* spontaneous = (const float*)d_in[2];
    const float* theta       = (const float*)d_in[3];
    const float* w           = (const float*)d_in[4];
    const float* alpha       = (const float*)d_in[5];
    float* out = (float*)d_out;

    cudaFuncSetAttribute(hawkes_kernel,
                         cudaFuncAttributeMaxDynamicSharedMemorySize, SMEM_BYTES);
    hawkes_kernel<<<1, NTHREADS, SMEM_BYTES>>>(seq_id, sequences, spontaneous,
                                               theta, w, alpha, out);
}

// round 5
// speedup vs baseline: 2.9645x; 1.1235x over previous
#include <cuda_runtime.h>
#include <cstdint>

#define NB_EVENT 2000
#define NB_TYPE  10
#define PRED_LEN 1000
#define RBLK     20
#define NBLK     50            // PRED_LEN / RBLK
#define SEQB     512           // tail window; w>=0.5 => older decay underflows to exactly 0 in f32
#define E0       (NB_EVENT - SEQB)

// ---- cross-kernel scratch (device globals; no allocation) ----
__device__ float g_c [PRED_LEN * NB_TYPE];   // c_{t,i}
__device__ float g_h [NBLK * NB_TYPE];       // h_t = u_{t,20}
__device__ float g_S0[NB_TYPE];
__device__ float g_R [RBLK * 100];           // R_0..R_19 (R_0 = B)
__device__ float g_P [100];                  // M^20
__device__ float g_St[NBLK * NB_TYPE];       // S_t

// ============================ K1: parallel precompute ============================
// blocks 0..49  : warp 0 runs t-block's 20-step u recurrence in registers
// blocks 50..57 : copy training block to out
// block  58     : S0 reduction (geometric decay, warp per type)
// block  59     : R chain (19 matmuls) + M^20 squaring chain
__global__ __launch_bounds__(256, 1)
void k1_kernel(const int* __restrict__ seq_id,
               const float* __restrict__ sequences,
               const float* __restrict__ spontaneous,
               const float* __restrict__ theta,
               const float* __restrict__ w,
               const float* __restrict__ alpha,
               float* __restrict__ out)
{
    const int bid = blockIdx.x;
    const int tid = threadIdx.x;
    const int sid = seq_id[0];
    const float* __restrict__ seq = sequences + (size_t)sid * NB_EVENT * NB_TYPE;

    if (bid < NBLK) {
        // ---- G: one t-block per block, warp 0 only, register-resident ----
        if (tid >= 32) return;
        const int  lane = tid;
        const bool act  = (lane < NB_TYPE);
        const int  k    = act ? lane : 0;

        float wk = 1.0f, th = 0.0f, ak = 0.0f, er = 1.0f, ew = 0.0f;
        if (act) {
            wk = w[sid * NB_TYPE + k];
            th = theta[sid * NB_TYPE + k];
            const float sp = spontaneous[sid * NB_TYPE + k];
            ew = expf(-wk);
            er = expf(-th);
            ak = sp / th * (1.0f - er);
        }
        // build B row / M row in registers (need som of all m via shuffle)
        const float som_self = 1.0f - ew;
        const float rwk = 1.0f / wk;
        float Brow[10], Mrow[10];
        #pragma unroll
        for (int m = 0; m < 10; m++) {
            const float som_m = __shfl_sync(0xFFFFFFFFu, som_self, m);
            const float al = act ? alpha[((size_t)sid * NB_TYPE + k) * NB_TYPE + m] : 0.0f;
            Brow[m] = rwk * al * som_m;
            Mrow[m] = ew * ((k == m ? 1.0f : 0.0f) + Brow[m]);
        }

        const int t = bid;
        float v = act ? ak * expf(-th * (float)(NB_EVENT + t * RBLK)) : 0.0f;
        float u = 0.0f;
        #pragma unroll
        for (int i = 0; i < RBLK; i++) {
            const float s0 = __shfl_sync(0xFFFFFFFFu, u, 0);
            const float s1 = __shfl_sync(0xFFFFFFFFu, u, 1);
            const float s2 = __shfl_sync(0xFFFFFFFFu, u, 2);
            const float s3 = __shfl_sync(0xFFFFFFFFu, u, 3);
            const float s4 = __shfl_sync(0xFFFFFFFFu, u, 4);
            const float s5 = __shfl_sync(0xFFFFFFFFu, u, 5);
            const float s6 = __shfl_sync(0xFFFFFFFFu, u, 6);
            const float s7 = __shfl_sync(0xFFFFFFFFu, u, 7);
            const float s8 = __shfl_sync(0xFFFFFFFFu, u, 8);
            const float s9 = __shfl_sync(0xFFFFFFFFu, u, 9);

            float ca = v;
            float ua = ew * v;
            ca += Brow[0]*s0; ua += Mrow[0]*s0;
            ca += Brow[1]*s1; ua += Mrow[1]*s1;
            ca += Brow[2]*s2; ua += Mrow[2]*s2;
            ca += Brow[3]*s3; ua += Mrow[3]*s3;
            ca += Brow[4]*s4; ua += Mrow[4]*s4;
            ca += Brow[5]*s5; ua += Mrow[5]*s5;
            ca += Brow[6]*s6; ua += Mrow[6]*s6;
            ca += Brow[7]*s7; ua += Mrow[7]*s7;
            ca += Brow[8]*s8; ua += Mrow[8]*s8;
            ca += Brow[9]*s9; ua += Mrow[9]*s9;

            if (act) g_c[(t * RBLK + i) * NB_TYPE + k] = ca;
            u = ua;
            v *= er;
        }
        if (act) g_h[t * NB_TYPE + k] = u;

    } else if (bid < 58) {
        // ---- copy training block (2048 threads total) ----
        const int gtid = (bid - 50) * 256 + tid;
        const float4* __restrict__ s4 = (const float4*)seq;
        float4* __restrict__ o4 = (float4*)out;
        for (int i = gtid; i < (NB_EVENT * NB_TYPE) / 4; i += 2048)
            o4[i] = s4[i];

    } else if (bid == 58) {
        // ---- S0: warp per type (warps 0..7 -> k=0..7; warps 0,1 again -> k=8,9) ----
        const int wid = tid >> 5, lane = tid & 31;
        for (int k = wid; k < NB_TYPE; k += 8) {
            const float wk = w[sid * NB_TYPE + k];
            float d = expf(-wk * (float)(1 + lane));        // decay at e = 1999 - lane
            const float r = expf(-32.0f * wk);
            float acc = 0.0f;
            #pragma unroll
            for (int j = 0; j < SEQB / 32; j++) {
                const int e = (NB_EVENT - 1 - lane) - 32 * j;
                acc += seq[e * NB_TYPE + k] * d;
                d *= r;
            }
            #pragma unroll
            for (int off = 16; off > 0; off >>= 1)
                acc += __shfl_xor_sync(0xFFFFFFFFu, acc, off);
            if (lane == 0) g_S0[k] = acc;
        }

    } else {
        // ---- matrices: R chain + M^20 ----
        __shared__ float sM[100], sRr[2][100];
        __shared__ float sM2[100], sM4[100], sM8[100], sM16[100];
        __shared__ float sEW[16], sOM[16], sRW[16];
        if (tid < NB_TYPE) {
            const float wk = w[sid * NB_TYPE + tid];
            const float e = expf(-wk);
            sEW[tid] = e;
            sOM[tid] = 1.0f - e;
            sRW[tid] = 1.0f / wk;
        }
        __syncthreads();
        if (tid < 100) {
            const int k = tid / 10, j = tid - (tid / 10) * 10;
            const float b = sRW[k] * alpha[((size_t)sid * NB_TYPE + k) * NB_TYPE + j] * sOM[j];
            sRr[0][tid] = b;
            sM[tid]  = sEW[k] * ((k == j ? 1.0f : 0.0f) + b);
            g_R[tid] = b;                                    // R_0 = B
        }
        __syncthreads();
        for (int rd = 0; rd < RBLK - 1; rd++) {              // 19 rounds
            if (tid < 100) {
                const int k = tid / 10, j = tid - (tid / 10) * 10;
                const float* __restrict__ Rc = sRr[rd & 1];
                float acc = 0.0f;
                #pragma unroll
                for (int m = 0; m < 10; m++)
                    acc += Rc[k * 10 + m] * sM[m * 10 + j];
                sRr[(rd & 1) ^ 1][tid] = acc;
                g_R[(rd + 1) * 100 + tid] = acc;
            } else if (tid < 200) {
                const int p = tid - 100;
                const int k = p / 10, j = p - (p / 10) * 10;
                float acc = 0.0f;
                if (rd == 0) {
                    #pragma unroll
                    for (int m = 0; m < 10; m++) acc += sM[k*10+m] * sM[m*10+j];
                    sM2[p] = acc;
                } else if (rd == 1) {
                    #pragma unroll
                    for (int m = 0; m < 10; m++) acc += sM2[k*10+m] * sM2[m*10+j];
                    sM4[p] = acc;
                } else if (rd == 2) {
                    #pragma unroll
                    for (int m = 0; m < 10; m++) acc += sM4[k*10+m] * sM4[m*10+j];
                    sM8[p] = acc;
                } else if (rd == 3) {
                    #pragma unroll
                    for (int m = 0; m < 10; m++) acc += sM8[k*10+m] * sM8[m*10+j];
                    sM16[p] = acc;
                } else if (rd == 4) {
                    #pragma unroll
                    for (int m = 0; m < 10; m++) acc += sM16[k*10+m] * sM4[m*10+j];
                    g_P[p] = acc;                            // M^20
                }
            }
            __syncthreads();
        }
    }
}

// ============================ K2: serial scan (1 warp) ============================
__global__ __launch_bounds__(32, 1)
void k2_kernel()
{
    __shared__ float sh [NBLK * NB_TYPE];
    __shared__ float sSt[NBLK * NB_TYPE];
    const int tid = threadIdx.x;
    const bool act = (tid < NB_TYPE);
    const int  k   = act ? tid : 0;

    for (int i = tid; i < NBLK * NB_TYPE; i += 32) sh[i] = g_h[i];

    float Pr[10];
    #pragma unroll
    for (int m = 0; m < 10; m++) Pr[m] = g_P[k * 10 + m];

    float S = act ? g_S0[k] : 0.0f;
    __syncwarp();
    if (act) sSt[k] = S;

    for (int t = 0; t < NBLK - 1; t++) {
        const float s0 = __shfl_sync(0xFFFFFFFFu, S, 0);
        const float s1 = __shfl_sync(0xFFFFFFFFu, S, 1);
        const float s2 = __shfl_sync(0xFFFFFFFFu, S, 2);
        const float s3 = __shfl_sync(0xFFFFFFFFu, S, 3);
        const float s4 = __shfl_sync(0xFFFFFFFFu, S, 4);
        const float s5 = __shfl_sync(0xFFFFFFFFu, S, 5);
        const float s6 = __shfl_sync(0xFFFFFFFFu, S, 6);
        const float s7 = __shfl_sync(0xFFFFFFFFu, S, 7);
        const float s8 = __shfl_sync(0xFFFFFFFFu, S, 8);
        const float s9 = __shfl_sync(0xFFFFFFFFu, S, 9);

        const float p0 = Pr[0]*s0, p1 = Pr[1]*s1, p2 = Pr[2]*s2, p3 = Pr[3]*s3;
        const float p4 = Pr[4]*s4, p5 = Pr[5]*s5, p6 = Pr[6]*s6, p7 = Pr[7]*s7;
        const float p8 = Pr[8]*s8, p9 = Pr[9]*s9;
        const float h  = sh[t * NB_TYPE + k];
        const float q0 = p0+p1, q1 = p2+p3, q2 = p4+p5, q3 = p6+p7, q4 = p8+p9;
        const float r0 = q0+q1, r1 = q2+q3, r2 = q4+h;
        S = (r0 + r1) + r2;
        if (act) sSt[(t + 1) * NB_TYPE + k] = S;
    }
    __syncwarp();
    for (int i = tid; i < NBLK * NB_TYPE; i += 32) g_St[i] = sSt[i];
}

// ============================ K3: parallel pred + store ============================
__global__ __launch_bounds__(256, 1)
void k3_kernel(float* __restrict__ out)
{
    __shared__ float sR [RBLK * 100];
    __shared__ float sSt[NBLK * NB_TYPE];
    const int tid = threadIdx.x;
    for (int i = tid; i < RBLK * 100; i += 256) sR[i] = g_R[i];
    for (int i = tid; i < NBLK * NB_TYPE; i += 256) sSt[i] = g_St[i];
    __syncthreads();

    const int idx = blockIdx.x * 256 + tid;
    if (idx < PRED_LEN * NB_TYPE) {
        const int t   = idx / (RBLK * NB_TYPE);
        const int rem = idx - t * (RBLK * NB_TYPE);
        const int i   = rem / NB_TYPE;
        const int k   = rem - i * NB_TYPE;
        float acc = g_c[idx];
        #pragma unroll
        for (int m = 0; m < 10; m++)
            acc += sR[i * 100 + k * 10 + m] * sSt[t * NB_TYPE + m];
        out[NB_EVENT * NB_TYPE + idx] = acc;
    }
}

extern "C" void kernel_launch(void* const* d_in, const int* in_sizes, int n_in,
                              void* d_out, int out_size)
{
    const int*   seq_id      = (const int*)  d_in[0];
    const float* sequences   = (const float*)d_in[1];
    const float* spontaneous = (const float*)d_in[2];
    const float* theta       = (const float*)d_in[3];
    const float* w           = (const float*)d_in[4];
    const float* alpha       = (const float*)d_in[5];
    float* out = (float*)d_out;

    k1_kernel<<<60, 256>>>(seq_id, sequences, spontaneous, theta, w, alpha, out);
    k2_kernel<<<1, 32>>>();
    k3_kernel<<<40, 256>>>(out);
}